// round 13
// baseline (speedup 1.0000x reference)
#include <cuda_runtime.h>
#include <math.h>

// Problem constants
#define BB   8
#define AA   192
#define DD   128
#define RELN 5
#define HH   128
#define EE   (BB*AA*AA)   // 294912 edges
#define KK   384          // K-dim of i/j precompute GEMM (3*D)

// Packed f32x2 helpers (sm_103a FFMA2 path)
#define PACK2(out, lo, hi)  asm("mov.b64 %0, {%1, %2};" : "=l"(out) : "f"(lo), "f"(hi))
#define UNPACK2(lo, hi, in) asm("mov.b64 {%0, %1}, %2;" : "=f"(lo), "=f"(hi) : "l"(in))
#define ADD2(d, a, b)       asm("add.rn.f32x2 %0, %1, %2;" : "=l"(d) : "l"(a), "l"(b))
#define MUL2(d, a, b)       asm("mul.rn.f32x2 %0, %1, %2;" : "=l"(d) : "l"(a), "l"(b))
#define FMA2(d, a, b, c)    asm("fma.rn.f32x2 %0, %1, %2, %3;" : "=l"(d) : "l"(a), "l"(b), "l"(c))

// Scratch (no cudaMalloc allowed)
__device__ float g_pre_i[BB*AA*HH];                 // f(i) partial, row-major [b][i][k]
__device__ __align__(16) float g_pre_jT[BB*AA*HH];  // f(j) transposed-packed [b][k/4][j][4]
__device__ float g_pre_g[BB*HH];                    // graph-context partial + b1

// ---------------------------------------------------------------------------
// Kernel 1: precompute pre_i / pre_jT  (+ fused pre_g tail blocks).
// 128 threads: col = tid, 8 rows per block.  Row-pairs packed f32x2:
// 4 FMA2 per K-step instead of 8 FMA (per-row sums bit-identical).
// which=0 -> pre_i row-major; which=1 -> pre_jT via smem transpose
// (coalesced 128B warp-stores).
// ---------------------------------------------------------------------------
#define CH   16            // K-chunk size
#define NCH  (KK/CH)       // 24 chunks
#define XPAD 12            // xs row stride in floats

__global__ __launch_bounds__(128) void precompute_kernel(
    const float* __restrict__ coord, const float* __restrict__ goal,
    const float* __restrict__ frontier, const float* __restrict__ gc,
    const float* __restrict__ W1, const float* __restrict__ b1)
{
    __shared__ __align__(16) float xs[KK][XPAD];   // [d][row 0..7]
    __shared__ float ws[2][CH][128];               // staged W1 chunks
    __shared__ float ts[HH * 9];                   // transpose staging (pad 9)

    const int tid = threadIdx.x;   // 0..127 == output col k

    if (blockIdx.x >= 384) {
        // ---- pre_g ----
        const int b = blockIdx.x - 384;
        float* gs = &xs[0][0];
        gs[tid] = gc[b * DD + tid];
        __syncthreads();
        float acc = b1[tid];
#pragma unroll 8
        for (int d = 0; d < DD; d++)
            acc = fmaf(gs[d], W1[(6 * DD + RELN + d) * HH + tid], acc);
        g_pre_g[b * HH + tid] = acc;
        return;
    }

    const int row0  = (blockIdx.x >> 1) * 8;
    const int which = blockIdx.x & 1;

    // Load x rows: coalesced global reads, xs[c][rr] smem layout
    for (int idx = tid; idx < 8 * KK; idx += 128) {
        const int rr = idx / KK, c = idx % KK;
        const int s = c >> 7, d = c & 127;
        const float* src = (s == 0) ? coord : ((s == 1) ? goal : frontier);
        xs[c][rr] = src[(row0 + rr) * DD + d];
    }

    const int wofs = which * 128;

    float tmp[CH];
#pragma unroll
    for (int dd = 0; dd < CH; dd++)
        tmp[dd] = W1[((dd >> 7) * 256 + wofs + (dd & 127)) * HH + tid];
#pragma unroll
    for (int dd = 0; dd < CH; dd++) ws[0][dd][tid] = tmp[dd];
    __syncthreads();

    unsigned long long ap0 = 0, ap1 = 0, ap2 = 0, ap3 = 0;  // row pairs (0,1)(2,3)(4,5)(6,7)

    for (int c = 0; c < NCH; c++) {
        const int buf = c & 1;
        if (c + 1 < NCH) {
            const int d0 = (c + 1) * CH;
#pragma unroll
            for (int dd = 0; dd < CH; dd++) {
                const int d = d0 + dd;
                tmp[dd] = W1[((d >> 7) * 256 + wofs + (d & 127)) * HH + tid];
            }
        }
        const int d0 = c * CH;
#pragma unroll
        for (int dd = 0; dd < CH; dd++) {
            const float w = ws[buf][dd][tid];
            unsigned long long wp;
            PACK2(wp, w, w);
            const ulonglong2 xlo = *(const ulonglong2*)&xs[d0 + dd][0];
            const ulonglong2 xhi = *(const ulonglong2*)&xs[d0 + dd][4];
            FMA2(ap0, wp, xlo.x, ap0);
            FMA2(ap1, wp, xlo.y, ap1);
            FMA2(ap2, wp, xhi.x, ap2);
            FMA2(ap3, wp, xhi.y, ap3);
        }
        if (c + 1 < NCH) {
#pragma unroll
            for (int dd = 0; dd < CH; dd++) ws[buf ^ 1][dd][tid] = tmp[dd];
        }
        __syncthreads();
    }

    float a0, a1, a2, a3, a4, a5, a6, a7;
    UNPACK2(a0, a1, ap0);
    UNPACK2(a2, a3, ap1);
    UNPACK2(a4, a5, ap2);
    UNPACK2(a6, a7, ap3);

    if (which == 0) {
        float* dst = g_pre_i;
        dst[(row0 + 0) * HH + tid] = a0;
        dst[(row0 + 1) * HH + tid] = a1;
        dst[(row0 + 2) * HH + tid] = a2;
        dst[(row0 + 3) * HH + tid] = a3;
        dst[(row0 + 4) * HH + tid] = a4;
        dst[(row0 + 5) * HH + tid] = a5;
        dst[(row0 + 6) * HH + tid] = a6;
        dst[(row0 + 7) * HH + tid] = a7;
    } else {
        // smem transpose, then coalesced 128B warp-stores to g_pre_jT
        const float av[8] = {a0, a1, a2, a3, a4, a5, a6, a7};
#pragma unroll
        for (int rr = 0; rr < 8; rr++)
            ts[tid * 9 + rr] = av[rr];       // stride 9 -> conflict-free
        __syncthreads();

        const int b  = row0 / AA;
        const int j0 = row0 % AA;
        const int wid  = tid >> 5, lane = tid & 31;
        const int kr = lane & 3, jj = lane >> 2;   // lane = jj*4 + kr
#pragma unroll
        for (int kq = wid; kq < 32; kq += 4) {
            const float v = ts[(kq * 4 + kr) * 9 + jj];
            g_pre_jT[((long)(b * 32 + kq) * AA + j0 + jj) * 4 + kr] = v;
        }
    }
}

// ---------------------------------------------------------------------------
// Kernel 2: edge MLP + masked softmax.  One block per (b, 4 i-rows).
// 192 threads, 6 warps; lane owns one j; per-lane accs over channels k
// (NO warp reductions in mainloop).  Tree-split f32x2 chains: per row-pair,
// u = (bias+pj)+r0w0+r1w1 and v = r2w2+r3w3+r4w4 computed independently,
// h = u+v  -> 4 independent depth-3 chains per thread (vs 2 depth-6).
// ---------------------------------------------------------------------------
__global__ __launch_bounds__(192) void edge_kernel(
    const float* __restrict__ rel,        // [B,A,A,5]
    const int* __restrict__ adj,          // [B,A,A] bool as int32
    const float* __restrict__ base,       // [B,A,A]
    const float* __restrict__ W1,
    const float* __restrict__ W2,         // [H,1]
    const float* __restrict__ b2,         // [1]
    float* __restrict__ out)              // [3*E]: weights | score(masked) | learned
{
    const int i0 = blockIdx.x * 4, b = blockIdx.y;
    const int tid  = threadIdx.x;         // 0..191
    const int wid  = tid >> 5, lane = tid & 31;
    const int j    = tid;

    __shared__ __align__(16) unsigned long long cst[HH * 8];
    // cst[k*8+0] = {bias_i0, bias_i1}; cst[k*8+1] = {bias_i2, bias_i3}
    // cst[k*8+2..6] = {w1r[r][k], w1r[r][k]}; cst[k*8+7] = {w2[k], w2[k]}
    __shared__ float red_s[6][8];
    __shared__ float fin[4];

    // ---- build cst (threads 0..127) ----
    if (tid < HH) {
        const int k = tid;
        const float pg = g_pre_g[b * HH + k];
        const float p0 = g_pre_i[(b * AA + i0 + 0) * HH + k] + pg;
        const float p1 = g_pre_i[(b * AA + i0 + 1) * HH + k] + pg;
        const float p2 = g_pre_i[(b * AA + i0 + 2) * HH + k] + pg;
        const float p3 = g_pre_i[(b * AA + i0 + 3) * HH + k] + pg;
        unsigned long long t;
        PACK2(t, p0, p1); cst[k * 8 + 0] = t;
        PACK2(t, p2, p3); cst[k * 8 + 1] = t;
#pragma unroll
        for (int r = 0; r < RELN; r++) {
            const float w = W1[(6 * DD + r) * HH + k];
            PACK2(t, w, w); cst[k * 8 + 2 + r] = t;
        }
        const float w2k = W2[k];
        PACK2(t, w2k, w2k); cst[k * 8 + 7] = t;
    }

    // ---- rel(i0..i0+3, j) into packed registers ----
    const float* rb = rel + ((long)(b * AA + i0) * AA + j) * RELN;
    unsigned long long rp01[RELN], rp23[RELN];
#pragma unroll
    for (int r = 0; r < RELN; r++) {
        PACK2(rp01[r], rb[r],                 rb[AA * RELN + r]);
        PACK2(rp23[r], rb[2 * AA * RELN + r], rb[3 * AA * RELN + r]);
    }
    const float b2v = b2[0];
    __syncthreads();

    // ---- mainloop over channels ----
    const float4* pjt = (const float4*)g_pre_jT + (long)(b * 32) * AA + j;
    float acc0 = 0.f, acc1 = 0.f, acc2 = 0.f, acc3 = 0.f;
    float4 cur = pjt[0];
#pragma unroll 2
    for (int kq = 0; kq < 32; kq++) {
        float4 nxt;
        if (kq < 31) nxt = pjt[(kq + 1) * AA];
#pragma unroll
        for (int q = 0; q < 4; q++) {
            const int k = kq * 4 + q;
            const ulonglong2* c = (const ulonglong2*)&cst[k * 8];
            const ulonglong2 cb   = c[0];   // {bias01, bias23}
            const ulonglong2 cw01 = c[1];   // {w0, w1}
            const ulonglong2 cw23 = c[2];   // {w2, w3}
            const ulonglong2 cw4v = c[3];   // {w4, w2pair}
            const float pj = (&cur.x)[q];
            unsigned long long pjp;
            PACK2(pjp, pj, pj);
            // 4 independent depth-3 chains (u01, v01, u23, v23)
            unsigned long long u01, v01, u23, v23;
            ADD2(u01, cb.x, pjp);
            ADD2(u23, cb.y, pjp);
            MUL2(v01, rp01[2], cw23.x);
            MUL2(v23, rp23[2], cw23.x);
            FMA2(u01, rp01[0], cw01.x, u01);
            FMA2(u23, rp23[0], cw01.x, u23);
            FMA2(v01, rp01[3], cw23.y, v01);
            FMA2(v23, rp23[3], cw23.y, v23);
            FMA2(u01, rp01[1], cw01.y, u01);
            FMA2(u23, rp23[1], cw01.y, u23);
            FMA2(v01, rp01[4], cw4v.x, v01);
            FMA2(v23, rp23[4], cw4v.x, v23);
            unsigned long long h01, h23;
            ADD2(h01, u01, v01);
            ADD2(h23, u23, v23);
            float h0, h1, h2, h3, w2k, w2d;
            UNPACK2(h0, h1, h01);
            UNPACK2(h2, h3, h23);
            UNPACK2(w2k, w2d, cw4v.y);
            h0 = fmaxf(h0, 0.f); h1 = fmaxf(h1, 0.f);
            h2 = fmaxf(h2, 0.f); h3 = fmaxf(h3, 0.f);
            acc0 = fmaf(h0, w2k, acc0);
            acc1 = fmaf(h1, w2k, acc1);
            acc2 = fmaf(h2, w2k, acc2);
            acc3 = fmaf(h3, w2k, acc3);
        }
        cur = nxt;
    }

    // ---- post phase: 4 rows fused (every thread owns j) ----
    const float lv[4] = {acc0 + b2v, acc1 + b2v, acc2 + b2v, acc3 + b2v};
    float sc[4], tmv[4];
    int   af[4], rbs[4];
#pragma unroll
    for (int ii = 0; ii < 4; ii++) {
        const int rbase = (b * AA + i0 + ii) * AA + j;
        rbs[ii] = rbase;
        af[ii]  = adj[rbase];
        sc[ii]  = af[ii] ? base[rbase] + lv[ii] : -1e9f;
        out[EE   + rbase] = sc[ii];   // score (masked, as reference returns)
        out[2*EE + rbase] = lv[ii];   // learned (unmasked)
    }

    float m[4] = {sc[0], sc[1], sc[2], sc[3]};
#pragma unroll
    for (int o = 16; o > 0; o >>= 1) {
#pragma unroll
        for (int ii = 0; ii < 4; ii++)
            m[ii] = fmaxf(m[ii], __shfl_xor_sync(0xffffffffu, m[ii], o));
    }
    if (lane == 0) {
#pragma unroll
        for (int ii = 0; ii < 4; ii++) red_s[wid][ii] = m[ii];
    }
    __syncthreads();
    if (tid < 4) {
        float x = red_s[0][tid];
#pragma unroll
        for (int w = 1; w < 6; w++) x = fmaxf(x, red_s[w][tid]);
        fin[tid] = x;
    }
    __syncthreads();

    float S[4], T[4];
#pragma unroll
    for (int ii = 0; ii < 4; ii++) {
        const float ev = __expf(sc[ii] - fin[ii]);  // masked -> exact 0 (or 1 if all-masked)
        tmv[ii] = af[ii] ? ev : 0.f;
        S[ii] = ev; T[ii] = tmv[ii];
    }
#pragma unroll
    for (int o = 16; o > 0; o >>= 1) {
#pragma unroll
        for (int ii = 0; ii < 4; ii++) {
            S[ii] += __shfl_xor_sync(0xffffffffu, S[ii], o);
            T[ii] += __shfl_xor_sync(0xffffffffu, T[ii], o);
        }
    }
    if (lane == 0) {
#pragma unroll
        for (int ii = 0; ii < 4; ii++) {
            red_s[wid][ii]     = S[ii];
            red_s[wid][4 + ii] = T[ii];
        }
    }
    __syncthreads();
    if (tid < 4) {
        float s = 0.f, t = 0.f;
#pragma unroll
        for (int w = 0; w < 6; w++) { s += red_s[w][tid]; t += red_s[w][4 + tid]; }
        // weight = adj*ev / (T + 1e-8*S)   (== reference (ev/S)*adj / (T/S + 1e-8))
        fin[tid] = 1.f / (t + 1e-8f * s);
    }
    __syncthreads();

#pragma unroll
    for (int ii = 0; ii < 4; ii++)
        out[rbs[ii]] = tmv[ii] * fin[ii];
}

// ---------------------------------------------------------------------------
extern "C" void kernel_launch(void* const* d_in, const int* in_sizes, int n_in,
                              void* d_out, int out_size)
{
    const float* coord    = (const float*)d_in[0];
    const float* goal     = (const float*)d_in[1];
    const float* frontier = (const float*)d_in[2];
    const float* rel      = (const float*)d_in[3];
    const int*   adj      = (const int*)d_in[4];
    const float* base     = (const float*)d_in[5];
    const float* gc       = (const float*)d_in[6];
    const float* W1       = (const float*)d_in[7];
    const float* b1       = (const float*)d_in[8];
    const float* W2       = (const float*)d_in[9];
    const float* b2       = (const float*)d_in[10];
    float* out = (float*)d_out;

    precompute_kernel<<<392, 128>>>(coord, goal, frontier, gc, W1, b1);
    dim3 grid(AA / 4, BB);
    edge_kernel<<<grid, 192>>>(rel, adj, base, W1, W2, b2, out);
}